// round 3
// baseline (speedup 1.0000x reference)
#include <cuda_runtime.h>

// Problem constants (fixed by the dataset)
#define BATCH 8192
#define HDIM  512
#define DPTH  16

// Scratch: per-sample partial losses + completion counter (__device__ globals
// per allocation rules). g_done is zero-initialized and reset by the last
// block each launch, so every graph replay starts clean.
__device__ float g_perword[BATCH];
__device__ unsigned int g_done;

// One CTA per sample. 512 threads = 16 warps; warp w computes the logit for
// huffman path row d = w. Weight loads are issued BEFORE the barrier (into
// registers) so they overlap the hidden->smem staging latency. The last CTA
// to finish performs the deterministic batch-mean reduction in-kernel.
__global__ __launch_bounds__(512) void hs_fused_kernel(
    const float* __restrict__ hidden,     // [BATCH, HDIM]
    const int*   __restrict__ target,     // [BATCH]
    const float* __restrict__ weights,    // [V, DPTH, HDIM]
    const float* __restrict__ codes,      // [V, DPTH]
    const int*   __restrict__ lengths,    // [V]
    float*       __restrict__ out)        // [1]
{
    const int b    = blockIdx.x;
    const int tid  = threadIdx.x;
    const int warp = tid >> 5;
    const int lane = tid & 31;

    __shared__ float sh[HDIM];
    __shared__ float slog[DPTH];
    __shared__ bool  is_last;

    const int word = __ldg(&target[b]);

    // Issue all weight loads first (independent of smem) to maximize MLP and
    // overlap with the hidden staging below.
    const float4* w4 =
        reinterpret_cast<const float4*>(weights + ((size_t)word * DPTH + warp) * HDIM);
    float4 w[4];
    #pragma unroll
    for (int i = 0; i < 4; i++)
        w[i] = w4[lane + 32 * i];

    // Stage hidden[b] into shared memory (128 float4 loads, threads 0..127)
    if (tid < HDIM / 4) {
        reinterpret_cast<float4*>(sh)[tid] =
            reinterpret_cast<const float4*>(hidden + (size_t)b * HDIM)[tid];
    }
    __syncthreads();

    // Dot product against smem-staged hidden
    const float4* sh4 = reinterpret_cast<const float4*>(sh);
    float acc = 0.0f;
    #pragma unroll
    for (int i = 0; i < 4; i++) {
        float4 h = sh4[lane + 32 * i];
        acc += w[i].x * h.x + w[i].y * h.y + w[i].z * h.z + w[i].w * h.w;
    }
    #pragma unroll
    for (int o = 16; o; o >>= 1)
        acc += __shfl_xor_sync(0xffffffff, acc, o);
    if (lane == 0) slog[warp] = acc;
    __syncthreads();

    // Warp 0: BCE-with-logits over the 16 path nodes, masked, mean over L,
    // write per-sample loss.
    if (warp == 0) {
        const int L = __ldg(&lengths[word]);
        float v = 0.0f;
        if (lane < DPTH) {
            float x = slog[lane];
            float t = __ldg(&codes[(size_t)word * DPTH + lane]);
            float bce = fmaxf(x, 0.0f) - x * t + log1pf(expf(-fabsf(x)));
            v = (lane < L) ? bce : 0.0f;
        }
        #pragma unroll
        for (int o = 16; o; o >>= 1)
            v += __shfl_xor_sync(0xffffffff, v, o);
        if (lane == 0) {
            g_perword[b] = v / (float)L;
            __threadfence();             // make loss visible before the ticket
        }
    }
    __syncthreads();

    // Last-block election
    if (tid == 0) {
        unsigned int t = atomicAdd(&g_done, 1u);
        is_last = (t == BATCH - 1);
    }
    __syncthreads();

    if (!is_last) return;

    // We are the last block: every other block's fence+atomic happened-before
    // our atomic read. Fence, then reduce all partials in a FIXED order
    // (deterministic regardless of which block is last).
    if (tid == 0) g_done = 0;            // reset for the next graph replay
    __threadfence();

    const float4* p4 = reinterpret_cast<const float4*>(g_perword);
    float acc2 = 0.0f;
    #pragma unroll
    for (int i = 0; i < (BATCH / 4) / 512; i++) {   // 4 float4 per thread
        float4 v4 = p4[tid + i * 512];
        acc2 += v4.x + v4.y + v4.z + v4.w;
    }
    #pragma unroll
    for (int o = 16; o; o >>= 1)
        acc2 += __shfl_xor_sync(0xffffffff, acc2, o);

    __shared__ float sred[16];
    if (lane == 0) sred[warp] = acc2;
    __syncthreads();
    if (warp == 0) {
        float v = (lane < 16) ? sred[lane] : 0.0f;
        #pragma unroll
        for (int o = 8; o; o >>= 1)
            v += __shfl_xor_sync(0xffffffff, v, o);
        if (lane == 0) out[0] = v / (float)BATCH;
    }
}

extern "C" void kernel_launch(void* const* d_in, const int* in_sizes, int n_in,
                              void* d_out, int out_size)
{
    const float* hidden  = (const float*)d_in[0];
    const int*   target  = (const int*)  d_in[1];
    const float* weights = (const float*)d_in[2];
    const float* codes   = (const float*)d_in[3];
    const int*   lengths = (const int*)  d_in[4];
    float* out = (float*)d_out;

    hs_fused_kernel<<<BATCH, 512>>>(hidden, target, weights, codes, lengths, out);
}

// round 4
// speedup vs baseline: 1.0264x; 1.0264x over previous
#include <cuda_runtime.h>

// Problem constants (fixed by the dataset)
#define BATCH 8192
#define HDIM  512
#define DPTH  16

// Scratch (__device__ globals per allocation rules). g_done starts 0 and is
// reset by the last block each launch -> clean state for every graph replay.
__device__ float g_perword[BATCH];
__device__ unsigned int g_done;

// One CTA per sample; 16 warps, warp w computes the logit for huffman row w.
// Load ordering matches the R2 winner (hidden stage, barrier, then weight
// loads) to keep MLP_p1 low and avoid cross-CTA L1tex-queue contention.
// Fence-free fused reduction: the per-sample loss store and the completion
// ticket are issued by the SAME thread with a release atomic, so no
// __threadfence (no CCTL.IVALL L1 flush) is ever executed.
__global__ __launch_bounds__(512) void hs_fused_kernel(
    const float* __restrict__ hidden,     // [BATCH, HDIM]
    const int*   __restrict__ target,     // [BATCH]
    const float* __restrict__ weights,    // [V, DPTH, HDIM]
    const float* __restrict__ codes,      // [V, DPTH]
    const int*   __restrict__ lengths,    // [V]
    float*       __restrict__ out)        // [1]
{
    const int b    = blockIdx.x;
    const int tid  = threadIdx.x;
    const int warp = tid >> 5;
    const int lane = tid & 31;

    __shared__ float sh[HDIM];
    __shared__ float slog[DPTH];
    __shared__ bool  is_last;

    const int word = target[b];

    // Stage hidden[b] into shared memory (128 float4 loads, threads 0..127)
    const float4* h4 = reinterpret_cast<const float4*>(hidden + (size_t)b * HDIM);
    if (tid < HDIM / 4) {
        reinterpret_cast<float4*>(sh)[tid] = h4[tid];
    }
    __syncthreads();

    // Dot product: warp `warp` handles weight row d = warp (contiguous 2KB)
    const float4* w4 =
        reinterpret_cast<const float4*>(weights + ((size_t)word * DPTH + warp) * HDIM);
    const float4* sh4 = reinterpret_cast<const float4*>(sh);

    float acc = 0.0f;
    #pragma unroll
    for (int i = 0; i < 4; i++) {   // 32 lanes x float4 per iter
        float4 w = w4[lane + 32 * i];
        float4 h = sh4[lane + 32 * i];
        acc += w.x * h.x + w.y * h.y + w.z * h.z + w.w * h.w;
    }
    #pragma unroll
    for (int o = 16; o; o >>= 1)
        acc += __shfl_xor_sync(0xffffffff, acc, o);
    if (lane == 0) slog[warp] = acc;
    __syncthreads();

    // Warp 0: BCE-with-logits, masked, mean over L; lane 0 stores the loss
    // and immediately takes the completion ticket (release-ordered).
    if (warp == 0) {
        const int L = lengths[word];
        float v = 0.0f;
        if (lane < DPTH) {
            float x = slog[lane];
            float t = codes[(size_t)word * DPTH + lane];
            float bce = fmaxf(x, 0.0f) - x * t + log1pf(expf(-fabsf(x)));
            v = (lane < L) ? bce : 0.0f;
        }
        #pragma unroll
        for (int o = 16; o; o >>= 1)
            v += __shfl_xor_sync(0xffffffff, v, o);
        if (lane == 0) {
            float loss = v / (float)L;
            // Store loss to L2 (bypass L1), then release-atomic the ticket.
            // Same thread issues both: the release orders the store without
            // any L1-flushing fence.
            asm volatile("st.global.cg.f32 [%0], %1;"
                         :: "l"(&g_perword[b]), "f"(loss) : "memory");
            unsigned int t;
            asm volatile("atom.release.gpu.global.add.u32 %0, [%1], %2;"
                         : "=r"(t) : "l"(&g_done), "r"(1u) : "memory");
            is_last = (t == BATCH - 1);
        }
    }
    __syncthreads();

    if (!is_last) return;

    // Last block: all 8191 other losses are release-ordered into L2 before
    // our ticket read. Read partials with ld.global.cg (L2 = coherence
    // point, no stale L1 lines possible: we never touched these addresses).
    if (tid == 0) g_done = 0;            // reset for next graph replay

    float acc2 = 0.0f;
    #pragma unroll
    for (int i = 0; i < BATCH / 512; i++)
        acc2 += __ldcg(&g_perword[tid + i * 512]);
    #pragma unroll
    for (int o = 16; o; o >>= 1)
        acc2 += __shfl_xor_sync(0xffffffff, acc2, o);

    __shared__ float sred[16];
    if (lane == 0) sred[warp] = acc2;
    __syncthreads();
    if (warp == 0) {
        float v = (lane < 16) ? sred[lane] : 0.0f;
        #pragma unroll
        for (int o = 8; o; o >>= 1)
            v += __shfl_xor_sync(0xffffffff, v, o);
        if (lane == 0) out[0] = v / (float)BATCH;
    }
}

extern "C" void kernel_launch(void* const* d_in, const int* in_sizes, int n_in,
                              void* d_out, int out_size)
{
    const float* hidden  = (const float*)d_in[0];
    const int*   target  = (const int*)  d_in[1];
    const float* weights = (const float*)d_in[2];
    const float* codes   = (const float*)d_in[3];
    const int*   lengths = (const int*)  d_in[4];
    float* out = (float*)d_out;

    hs_fused_kernel<<<BATCH, 512>>>(hidden, target, weights, codes, lengths, out);
}

// round 6
// speedup vs baseline: 1.4614x; 1.4238x over previous
#include <cuda_runtime.h>

// Problem constants (fixed by the dataset)
#define BATCH 8192
#define HDIM  512
#define DPTH  16
#define WPB   8                 // warps per block
#define NBLK  (BATCH / WPB)     // 1024 CTAs

// Per-sample losses (scratch; __device__ global per allocation rules)
__device__ float g_perword[BATCH];

// Warp-per-sample streaming kernel: no smem, no __syncthreads.
// Each warp loads hidden[b] into registers (lane owns cols {4l..4l+3} of each
// 128-col chunk), streams the 16 weight rows two at a time (8 LDG.128 in
// flight), accumulates 16 per-lane dot partials, then does a transposed
// cross-lane tree reduction so lane l holds the full logit for d = l & 15.
__global__ __launch_bounds__(256) void hs_main_kernel(
    const float* __restrict__ hidden,     // [BATCH, HDIM]
    const int*   __restrict__ target,     // [BATCH]
    const float* __restrict__ weights,    // [V, DPTH, HDIM]
    const float* __restrict__ codes,      // [V, DPTH]
    const int*   __restrict__ lengths)    // [V]
{
    const int warp = threadIdx.x >> 5;
    const int lane = threadIdx.x & 31;
    const int b    = blockIdx.x * WPB + warp;

    const int word = target[b];           // broadcast load

    // hidden[b]: 128 float4 per row; lane takes {lane, lane+32, lane+64, lane+96}
    const float4* hp = reinterpret_cast<const float4*>(hidden + (size_t)b * HDIM);
    float4 h[4];
    #pragma unroll
    for (int i = 0; i < 4; i++) h[i] = hp[lane + 32 * i];

    const float4* wp =
        reinterpret_cast<const float4*>(weights + (size_t)word * DPTH * HDIM);

    float acc[DPTH];
    #pragma unroll
    for (int d = 0; d < DPTH; d += 2) {
        float4 a[4], c[4];
        #pragma unroll
        for (int i = 0; i < 4; i++) a[i] = wp[(size_t)d * 128 + lane + 32 * i];
        #pragma unroll
        for (int i = 0; i < 4; i++) c[i] = wp[(size_t)(d + 1) * 128 + lane + 32 * i];
        float s0 = 0.0f, s1 = 0.0f;
        #pragma unroll
        for (int i = 0; i < 4; i++) {
            s0 += a[i].x * h[i].x + a[i].y * h[i].y + a[i].z * h[i].z + a[i].w * h[i].w;
            s1 += c[i].x * h[i].x + c[i].y * h[i].y + c[i].z * h[i].z + c[i].w * h[i].w;
        }
        acc[d]     = s0;
        acc[d + 1] = s1;
    }

    // ---- Transposed cross-lane reduction ----
    // Step 0: fold the two 16-lane halves (full add of all 16 values).
    #pragma unroll
    for (int i = 0; i < 16; i++)
        acc[i] += __shfl_xor_sync(0xffffffff, acc[i], 16);
    // Split steps: after step with bit bb, lanes with (lane & bb) own the high
    // half. Final: lane l holds logit for d = l & 15.
    #pragma unroll
    for (int i = 0; i < 8; i++) {
        const bool hi = (lane & 8);
        float send = hi ? acc[i] : acc[i + 8];
        float o = __shfl_xor_sync(0xffffffff, send, 8);
        acc[i] = (hi ? acc[i + 8] : acc[i]) + o;
    }
    #pragma unroll
    for (int i = 0; i < 4; i++) {
        const bool hi = (lane & 4);
        float send = hi ? acc[i] : acc[i + 4];
        float o = __shfl_xor_sync(0xffffffff, send, 4);
        acc[i] = (hi ? acc[i + 4] : acc[i]) + o;
    }
    #pragma unroll
    for (int i = 0; i < 2; i++) {
        const bool hi = (lane & 2);
        float send = hi ? acc[i] : acc[i + 2];
        float o = __shfl_xor_sync(0xffffffff, send, 2);
        acc[i] = (hi ? acc[i + 2] : acc[i]) + o;
    }
    {
        const bool hi = (lane & 1);
        float send = hi ? acc[0] : acc[1];
        float o = __shfl_xor_sync(0xffffffff, send, 1);
        acc[0] = (hi ? acc[1] : acc[0]) + o;
    }

    // ---- BCE-with-logits: lane l handles path node d = l & 15 ----
    const int   d = lane & 15;
    const float x = acc[0];
    const float t = codes[(size_t)word * DPTH + d];   // 64B line, broadcast halves
    const int   L = lengths[word];
    float bce = fmaxf(x, 0.0f) - x * t + log1pf(expf(-fabsf(x)));
    float v   = (d < L) ? bce : 0.0f;
    #pragma unroll
    for (int o = 8; o; o >>= 1)       // sum within each 16-lane half
        v += __shfl_xor_sync(0xffffffff, v, o);
    if (lane == 0)
        g_perword[b] = v / (float)L;
}

// Deterministic single-CTA reduction of the 8192 partials -> mean
__global__ __launch_bounds__(1024) void hs_reduce_kernel(float* __restrict__ out)
{
    __shared__ float s[32];
    const int tid = threadIdx.x;
    const float4* p4 = reinterpret_cast<const float4*>(g_perword);
    float acc = 0.0f;
    #pragma unroll
    for (int i = 0; i < (BATCH / 4) / 1024; i++) {   // 2 float4 per thread
        float4 v4 = p4[tid + i * 1024];
        acc += v4.x + v4.y + v4.z + v4.w;
    }
    #pragma unroll
    for (int o = 16; o; o >>= 1)
        acc += __shfl_xor_sync(0xffffffff, acc, o);
    if ((tid & 31) == 0) s[tid >> 5] = acc;
    __syncthreads();
    if (tid < 32) {
        float v = s[tid];
        #pragma unroll
        for (int o = 16; o; o >>= 1)
            v += __shfl_xor_sync(0xffffffff, v, o);
        if (tid == 0) out[0] = v / (float)BATCH;
    }
}

extern "C" void kernel_launch(void* const* d_in, const int* in_sizes, int n_in,
                              void* d_out, int out_size)
{
    const float* hidden  = (const float*)d_in[0];
    const int*   target  = (const int*)  d_in[1];
    const float* weights = (const float*)d_in[2];
    const float* codes   = (const float*)d_in[3];
    const int*   lengths = (const int*)  d_in[4];
    float* out = (float*)d_out;

    hs_main_kernel<<<NBLK, 256>>>(hidden, target, weights, codes, lengths);
    hs_reduce_kernel<<<1, 1024>>>(out);
}